// round 4
// baseline (speedup 1.0000x reference)
#include <cuda_runtime.h>
#include <cuda_bf16.h>

// values[m] = sum_n exp(-0.5 * sum_d (p[m,d]-pos[n,d])^2 / (exp(ls[n,d])^2+eps)) * I[n]
//
// Log2-domain expansion per gaussian n:
//   civ_d = -0.5*log2(e) / (exp(ls_d)^2 + eps)
//   a_d = civ_d, b_d = -2*civ_d*s_d, cc = 0.5*(sum_d civ_d*s_d^2 + log2 I)
//   arg = sum_d (a_d*p_d^2 + b_d*p_d) + 2*cc ; contribution = exp2(arg)
// Inner loop: 3-deep fma.rn.f32x2 chain on ((a_d,b_d),(p_d^2,p_d)), lo+hi, ex2, add.
//
// Single fused kernel: every block recomputes the 1024-gaussian coefficient
// table into smem (cheap: ~40 flops/thread, inputs L2-resident), then
// block = 8 gaussian-segments x 64 threads, 2 points per thread (128 pts/block).
// smem: 32KB params + 4KB reduction. grid=391 -> single wave, ~2.6 blocks/SM.

#define SEGS 8
#define SEG_THREADS 64
#define BLOCK_THREADS (SEGS * SEG_THREADS)      // 512
#define PTS_PER_BLOCK (2 * SEG_THREADS)         // 128

__device__ __forceinline__ unsigned long long ffma2(unsigned long long a,
                                                    unsigned long long b,
                                                    unsigned long long c) {
    unsigned long long d;
    asm("fma.rn.f32x2 %0, %1, %2, %3;" : "=l"(d) : "l"(a), "l"(b), "l"(c));
    return d;
}
__device__ __forceinline__ unsigned long long pack2(float lo, float hi) {
    unsigned long long d;
    asm("mov.b64 %0, {%1, %2};" : "=l"(d) : "f"(lo), "f"(hi));
    return d;
}
__device__ __forceinline__ float pair_hsum(unsigned long long v) {
    float lo, hi;
    asm("mov.b64 {%0, %1}, %2;" : "=f"(lo), "=f"(hi) : "l"(v));
    return lo + hi;
}
__device__ __forceinline__ float ex2(float x) {
    float r;
    asm("ex2.approx.f32 %0, %1;" : "=f"(r) : "f"(x));
    return r;
}

__global__ void __launch_bounds__(BLOCK_THREADS)
eval_kernel(const float* __restrict__ points,
            const float* __restrict__ positions,
            const float* __restrict__ log_scales,
            const float* __restrict__ intensities,
            float* __restrict__ out,
            int M, int N) {
    extern __shared__ float sp[];   // [8*N] params, then [SEGS*PTS_PER_BLOCK] reduction
    float* red = sp + 8 * N;

    // ---- in-block prep: coefficient table for all N gaussians ----
    const float LOG2E = 1.4426950408889634f;
    for (int n = threadIdx.x; n < N; n += BLOCK_THREADS) {
        float c = 0.0f;
        float4 q0, q1;
        float av[3], bv[3];
#pragma unroll
        for (int d = 0; d < 3; d++) {
            float s = __expf(log_scales[3 * n + d]);
            float civ = -0.5f * LOG2E / (s * s + 1e-6f);
            float p = positions[3 * n + d];
            av[d] = civ;
            bv[d] = -2.0f * civ * p;
            c = fmaf(civ, p * p, c);
        }
        float cc = 0.5f * (c + __log2f(intensities[n]));
        q0 = make_float4(av[0], bv[0], av[1], bv[1]);
        q1 = make_float4(av[2], bv[2], cc, cc);
        ((float4*)sp)[2 * n]     = q0;
        ((float4*)sp)[2 * n + 1] = q1;
    }
    __syncthreads();

    // ---- main loop: 2 points/thread, 1/8 of gaussians per segment ----
    int pt  = threadIdx.x & (SEG_THREADS - 1);
    int seg = threadIdx.x / SEG_THREADS;
    int m0 = blockIdx.x * PTS_PER_BLOCK + pt;
    int m1 = m0 + SEG_THREADS;

    float px0 = 0.f, py0 = 0.f, pz0 = 0.f, px1 = 0.f, py1 = 0.f, pz1 = 0.f;
    if (m0 < M) { px0 = points[3*m0]; py0 = points[3*m0+1]; pz0 = points[3*m0+2]; }
    if (m1 < M) { px1 = points[3*m1]; py1 = points[3*m1+1]; pz1 = points[3*m1+2]; }

    unsigned long long vx0 = pack2(px0*px0, px0), vy0 = pack2(py0*py0, py0), vz0 = pack2(pz0*pz0, pz0);
    unsigned long long vx1 = pack2(px1*px1, px1), vy1 = pack2(py1*py1, py1), vz1 = pack2(pz1*pz1, pz1);

    int chunk = N / SEGS;
    const ulonglong2* g = (const ulonglong2*)sp + (size_t)seg * chunk * 2;

    float acc0 = 0.0f, acc1 = 0.0f;
#pragma unroll 8
    for (int n = 0; n < chunk; n++) {
        ulonglong2 u0 = g[2 * n];      // (ax,bx) , (ay,by)
        ulonglong2 u1 = g[2 * n + 1];  // (az,bz) , (cc,cc)
        unsigned long long r0 = ffma2(u0.x, vx0, u1.y);
        unsigned long long r1 = ffma2(u0.x, vx1, u1.y);
        r0 = ffma2(u0.y, vy0, r0);
        r1 = ffma2(u0.y, vy1, r1);
        r0 = ffma2(u1.x, vz0, r0);
        r1 = ffma2(u1.x, vz1, r1);
        acc0 += ex2(pair_hsum(r0));
        acc1 += ex2(pair_hsum(r1));
    }

    red[seg * PTS_PER_BLOCK + pt] = acc0;
    red[seg * PTS_PER_BLOCK + pt + SEG_THREADS] = acc1;
    __syncthreads();

    if (threadIdx.x < PTS_PER_BLOCK) {
        int m = blockIdx.x * PTS_PER_BLOCK + threadIdx.x;
        if (m < M) {
            float s = 0.0f;
#pragma unroll
            for (int sgi = 0; sgi < SEGS; sgi++)
                s += red[sgi * PTS_PER_BLOCK + threadIdx.x];
            out[m] = s;
        }
    }
}

extern "C" void kernel_launch(void* const* d_in, const int* in_sizes, int n_in,
                              void* d_out, int out_size) {
    const float* points      = (const float*)d_in[0];  // [M,3]
    const float* positions   = (const float*)d_in[1];  // [N,3]
    const float* log_scales  = (const float*)d_in[2];  // [N,3]
    const float* intensities = (const float*)d_in[3];  // [N]
    float* out = (float*)d_out;

    int M = in_sizes[0] / 3;
    int N = in_sizes[3];

    int grid = (M + PTS_PER_BLOCK - 1) / PTS_PER_BLOCK;
    size_t smem = (size_t)8 * N * sizeof(float) + SEGS * PTS_PER_BLOCK * sizeof(float);
    eval_kernel<<<grid, BLOCK_THREADS, smem>>>(points, positions, log_scales,
                                               intensities, out, M, N);
}

// round 5
// speedup vs baseline: 1.0899x; 1.0899x over previous
#include <cuda_runtime.h>
#include <cuda_bf16.h>

// values[m] = sum_n exp(-0.5 * sum_d (p[m,d]-pos[n,d])^2 / (exp(ls[n,d])^2+eps)) * I[n]
//
// Log2-domain expansion per gaussian n:
//   civ_d = -0.5*log2(e)/(exp(ls_d)^2+eps);  a_d=civ_d; b_d=-2*civ_d*s_d
//   cc = sum_d civ_d*s_d^2 + log2(I)
//   arg = sum_d (a_d*p_d^2 + b_d*p_d) + cc ;  contribution = exp2(arg)
//
// TWO GAUSSIANS PER FFMA2 LANE: point values broadcast into both lanes,
// lane0/lane1 hold coefficients of gaussian pair (2j, 2j+1). 6 chained
// fma.rn.f32x2 (init = (cc0,cc1)) yield both args -> 2x ex2 -> add.rn.f32x2
// into a pair accumulator. No per-eval horizontal sum.
//
// smem per pair j (64B): f4[0]=(ax0,ax1,ay0,ay1) f4[1]=(az0,az1,bx0,bx1)
//                        f4[2]=(by0,by1,bz0,bz1) f4[3]=(cc0,cc1,0,0)

#define MAX_N 4096
__device__ float4 g_pairs[2 * MAX_N];   // 4 float4 per gaussian-pair, N/2 pairs

__global__ void prep_kernel(const float* __restrict__ positions,
                            const float* __restrict__ log_scales,
                            const float* __restrict__ intensities,
                            int N) {
    int j = blockIdx.x * blockDim.x + threadIdx.x;
    if (j >= N / 2) return;
    const float LOG2E = 1.4426950408889634f;
    float a[2][3], b[2][3], cc[2];
#pragma unroll
    for (int k = 0; k < 2; k++) {
        int n = 2 * j + k;
        float c = 0.0f;
#pragma unroll
        for (int d = 0; d < 3; d++) {
            float s = __expf(log_scales[3 * n + d]);
            float civ = -0.5f * LOG2E / (s * s + 1e-6f);
            float p = positions[3 * n + d];
            a[k][d] = civ;
            b[k][d] = -2.0f * civ * p;
            c = fmaf(civ, p * p, c);
        }
        cc[k] = c + __log2f(intensities[n]);  // I=0 -> -inf -> exp2 -> 0, correct
    }
    g_pairs[4 * j + 0] = make_float4(a[0][0], a[1][0], a[0][1], a[1][1]); // ax|ay
    g_pairs[4 * j + 1] = make_float4(a[0][2], a[1][2], b[0][0], b[1][0]); // az|bx
    g_pairs[4 * j + 2] = make_float4(b[0][1], b[1][1], b[0][2], b[1][2]); // by|bz
    g_pairs[4 * j + 3] = make_float4(cc[0], cc[1], 0.0f, 0.0f);           // cc
}

__device__ __forceinline__ unsigned long long ffma2(unsigned long long a,
                                                    unsigned long long b,
                                                    unsigned long long c) {
    unsigned long long d;
    asm("fma.rn.f32x2 %0, %1, %2, %3;" : "=l"(d) : "l"(a), "l"(b), "l"(c));
    return d;
}
__device__ __forceinline__ unsigned long long addx2(unsigned long long a,
                                                    unsigned long long b) {
    unsigned long long d;
    asm("add.rn.f32x2 %0, %1, %2;" : "=l"(d) : "l"(a), "l"(b));
    return d;
}
__device__ __forceinline__ unsigned long long pack2(float lo, float hi) {
    unsigned long long d;
    asm("mov.b64 %0, {%1, %2};" : "=l"(d) : "f"(lo), "f"(hi));
    return d;
}
__device__ __forceinline__ float pair_hsum(unsigned long long v) {
    float lo, hi;
    asm("mov.b64 {%0, %1}, %2;" : "=f"(lo), "=f"(hi) : "l"(v));
    return lo + hi;
}
__device__ __forceinline__ void unpack2(unsigned long long v, float& lo, float& hi) {
    asm("mov.b64 {%0, %1}, %2;" : "=f"(lo), "=f"(hi) : "l"(v));
}
__device__ __forceinline__ float ex2(float x) {
    float r;
    asm("ex2.approx.f32 %0, %1;" : "=f"(r) : "f"(x));
    return r;
}

#define SEGS 4
#define SEG_THREADS 64
#define BLOCK_THREADS (SEGS * SEG_THREADS)   // 256
#define PTS_PER_BLOCK SEG_THREADS            // 64 (1 point per thread)

__global__ void __launch_bounds__(BLOCK_THREADS)
eval_kernel(const float* __restrict__ points,
            float* __restrict__ out,
            int M, int N) {
    extern __shared__ float sp[];   // 8*N floats params + BLOCK_THREADS reduction
    float* red = sp + 8 * N;
    {
        float4* sp4 = (float4*)sp;
        for (int i = threadIdx.x; i < 2 * N; i += BLOCK_THREADS) sp4[i] = g_pairs[i];
    }
    __syncthreads();

    int pt  = threadIdx.x & (SEG_THREADS - 1);
    int seg = threadIdx.x / SEG_THREADS;
    int m = blockIdx.x * PTS_PER_BLOCK + pt;

    float px = 0.f, py = 0.f, pz = 0.f;
    if (m < M) { px = points[3*m]; py = points[3*m+1]; pz = points[3*m+2]; }

    unsigned long long vxx = pack2(px*px, px*px);
    unsigned long long vyy = pack2(py*py, py*py);
    unsigned long long vzz = pack2(pz*pz, pz*pz);
    unsigned long long vx  = pack2(px, px);
    unsigned long long vy  = pack2(py, py);
    unsigned long long vz  = pack2(pz, pz);

    int chunkPairs = (N / 2) / SEGS;   // 128
    const ulonglong2* g = (const ulonglong2*)sp + (size_t)seg * chunkPairs * 4;

    unsigned long long acc2 = pack2(0.0f, 0.0f);
#pragma unroll 4
    for (int j = 0; j < chunkPairs; j++) {
        ulonglong2 u0 = g[4 * j + 0];    // ax01 | ay01
        ulonglong2 u1 = g[4 * j + 1];    // az01 | bx01
        ulonglong2 u2 = g[4 * j + 2];    // by01 | bz01
        unsigned long long cc01 =
            *((const unsigned long long*)(g + 4 * j + 3));  // cc01 (LDS.64)

        unsigned long long r = ffma2(u0.x, vxx, cc01);
        r = ffma2(u0.y, vyy, r);
        r = ffma2(u1.x, vzz, r);
        r = ffma2(u1.y, vx,  r);
        r = ffma2(u2.x, vy,  r);
        r = ffma2(u2.y, vz,  r);

        float lo, hi;
        unpack2(r, lo, hi);
        acc2 = addx2(acc2, pack2(ex2(lo), ex2(hi)));
    }

    red[seg * PTS_PER_BLOCK + pt] = pair_hsum(acc2);
    __syncthreads();

    if (threadIdx.x < PTS_PER_BLOCK) {
        int mm = blockIdx.x * PTS_PER_BLOCK + threadIdx.x;
        if (mm < M) {
            float s = 0.0f;
#pragma unroll
            for (int sg = 0; sg < SEGS; sg++)
                s += red[sg * PTS_PER_BLOCK + threadIdx.x];
            out[mm] = s;
        }
    }
}

extern "C" void kernel_launch(void* const* d_in, const int* in_sizes, int n_in,
                              void* d_out, int out_size) {
    const float* points      = (const float*)d_in[0];  // [M,3]
    const float* positions   = (const float*)d_in[1];  // [N,3]
    const float* log_scales  = (const float*)d_in[2];  // [N,3]
    const float* intensities = (const float*)d_in[3];  // [N]
    float* out = (float*)d_out;

    int M = in_sizes[0] / 3;
    int N = in_sizes[3];

    prep_kernel<<<(N / 2 + 255) / 256, 256>>>(positions, log_scales, intensities, N);

    int grid = (M + PTS_PER_BLOCK - 1) / PTS_PER_BLOCK;
    size_t smem = (size_t)8 * N * sizeof(float) + BLOCK_THREADS * sizeof(float);
    eval_kernel<<<grid, BLOCK_THREADS, smem>>>(points, out, M, N);
}

// round 6
// speedup vs baseline: 1.4126x; 1.2960x over previous
#include <cuda_runtime.h>
#include <cuda_bf16.h>

// values[m] = sum_n exp(-0.5 * sum_d (p[m,d]-pos[n,d])^2 / (exp(ls[n,d])^2+eps)) * I[n]
//
// Log2-domain expansion per gaussian n:
//   civ_d = -0.5*log2(e)/(exp(ls_d)^2+eps);  a_d=civ_d; b_d=-2*civ_d*s_d
//   cc = sum_d civ_d*s_d^2 + log2(I);  arg = sum_d (a_d*p_d^2 + b_d*p_d) + cc
//   contribution = exp2(arg)
//
// Two gaussians per FFMA2 lane (point value broadcast to both lanes), and
// TWO POINTS PER THREAD sharing each coefficient load: 4 LDS feed 4 evals.
// Segmentation is ACROSS blocks (blockIdx.y = 1/8 of the gaussian list), so
// smem per block is only a 4KB slice -> occupancy no longer smem-capped.
// Each block computes its own slice in-smem (64 pairs, cheap), partial sums
// combined with atomicAdd into a memset-zeroed output.

#define SEGS 8
#define BLOCK_THREADS 256
#define PTS_PER_BLOCK (2 * BLOCK_THREADS)    // 512

__device__ __forceinline__ unsigned long long ffma2(unsigned long long a,
                                                    unsigned long long b,
                                                    unsigned long long c) {
    unsigned long long d;
    asm("fma.rn.f32x2 %0, %1, %2, %3;" : "=l"(d) : "l"(a), "l"(b), "l"(c));
    return d;
}
__device__ __forceinline__ unsigned long long addx2(unsigned long long a,
                                                    unsigned long long b) {
    unsigned long long d;
    asm("add.rn.f32x2 %0, %1, %2;" : "=l"(d) : "l"(a), "l"(b));
    return d;
}
__device__ __forceinline__ unsigned long long pack2(float lo, float hi) {
    unsigned long long d;
    asm("mov.b64 %0, {%1, %2};" : "=l"(d) : "f"(lo), "f"(hi));
    return d;
}
__device__ __forceinline__ float pair_hsum(unsigned long long v) {
    float lo, hi;
    asm("mov.b64 {%0, %1}, %2;" : "=f"(lo), "=f"(hi) : "l"(v));
    return lo + hi;
}
__device__ __forceinline__ void unpack2(unsigned long long v, float& lo, float& hi) {
    asm("mov.b64 {%0, %1}, %2;" : "=f"(lo), "=f"(hi) : "l"(v));
}
__device__ __forceinline__ float ex2(float x) {
    float r;
    asm("ex2.approx.f32 %0, %1;" : "=f"(r) : "f"(x));
    return r;
}

__global__ void __launch_bounds__(BLOCK_THREADS)
eval_kernel(const float* __restrict__ points,
            const float* __restrict__ positions,
            const float* __restrict__ log_scales,
            const float* __restrict__ intensities,
            float* __restrict__ out,
            int M, int N) {
    // smem slice: pairsPerSeg pairs * 4 float4 = N/SEGS/2 * 64 bytes (4KB @ N=1024)
    extern __shared__ float4 sp4[];
    int pairsPerSeg = (N / 2) / SEGS;            // 64
    int seg = blockIdx.y;

    // ---- build this segment's coefficient slice (64 pairs) ----
    const float LOG2E = 1.4426950408889634f;
    for (int t = threadIdx.x; t < pairsPerSeg; t += BLOCK_THREADS) {
        int j = seg * pairsPerSeg + t;           // global pair index
        float a[2][3], b[2][3], cc[2];
#pragma unroll
        for (int k = 0; k < 2; k++) {
            int n = 2 * j + k;
            float c = 0.0f;
#pragma unroll
            for (int d = 0; d < 3; d++) {
                float s = __expf(log_scales[3 * n + d]);
                float civ = -0.5f * LOG2E / (s * s + 1e-6f);
                float p = positions[3 * n + d];
                a[k][d] = civ;
                b[k][d] = -2.0f * civ * p;
                c = fmaf(civ, p * p, c);
            }
            cc[k] = c + __log2f(intensities[n]); // I=0 -> -inf -> exp2 -> 0
        }
        sp4[4 * t + 0] = make_float4(a[0][0], a[1][0], a[0][1], a[1][1]); // ax|ay
        sp4[4 * t + 1] = make_float4(a[0][2], a[1][2], b[0][0], b[1][0]); // az|bx
        sp4[4 * t + 2] = make_float4(b[0][1], b[1][1], b[0][2], b[1][2]); // by|bz
        sp4[4 * t + 3] = make_float4(cc[0], cc[1], 0.0f, 0.0f);           // cc
    }
    __syncthreads();

    // ---- main loop: 2 points per thread over this segment's pairs ----
    int m0 = blockIdx.x * PTS_PER_BLOCK + threadIdx.x;
    int m1 = m0 + BLOCK_THREADS;

    float px0 = 0.f, py0 = 0.f, pz0 = 0.f, px1 = 0.f, py1 = 0.f, pz1 = 0.f;
    if (m0 < M) { px0 = points[3*m0]; py0 = points[3*m0+1]; pz0 = points[3*m0+2]; }
    if (m1 < M) { px1 = points[3*m1]; py1 = points[3*m1+1]; pz1 = points[3*m1+2]; }

    unsigned long long vxx0 = pack2(px0*px0, px0*px0), vx0 = pack2(px0, px0);
    unsigned long long vyy0 = pack2(py0*py0, py0*py0), vy0 = pack2(py0, py0);
    unsigned long long vzz0 = pack2(pz0*pz0, pz0*pz0), vz0 = pack2(pz0, pz0);
    unsigned long long vxx1 = pack2(px1*px1, px1*px1), vx1 = pack2(px1, px1);
    unsigned long long vyy1 = pack2(py1*py1, py1*py1), vy1 = pack2(py1, py1);
    unsigned long long vzz1 = pack2(pz1*pz1, pz1*pz1), vz1 = pack2(pz1, pz1);

    const ulonglong2* g = (const ulonglong2*)sp4;
    unsigned long long acc0 = pack2(0.0f, 0.0f);
    unsigned long long acc1 = pack2(0.0f, 0.0f);

#pragma unroll 4
    for (int j = 0; j < pairsPerSeg; j++) {
        ulonglong2 u0 = g[4 * j + 0];    // ax01 | ay01
        ulonglong2 u1 = g[4 * j + 1];    // az01 | bx01
        ulonglong2 u2 = g[4 * j + 2];    // by01 | bz01
        unsigned long long cc01 = *((const unsigned long long*)(g + 4 * j + 3));

        unsigned long long r0 = ffma2(u0.x, vxx0, cc01);
        unsigned long long r1 = ffma2(u0.x, vxx1, cc01);
        r0 = ffma2(u0.y, vyy0, r0);
        r1 = ffma2(u0.y, vyy1, r1);
        r0 = ffma2(u1.x, vzz0, r0);
        r1 = ffma2(u1.x, vzz1, r1);
        r0 = ffma2(u1.y, vx0,  r0);
        r1 = ffma2(u1.y, vx1,  r1);
        r0 = ffma2(u2.x, vy0,  r0);
        r1 = ffma2(u2.x, vy1,  r1);
        r0 = ffma2(u2.y, vz0,  r0);
        r1 = ffma2(u2.y, vz1,  r1);

        float lo0, hi0, lo1, hi1;
        unpack2(r0, lo0, hi0);
        unpack2(r1, lo1, hi1);
        acc0 = addx2(acc0, pack2(ex2(lo0), ex2(hi0)));
        acc1 = addx2(acc1, pack2(ex2(lo1), ex2(hi1)));
    }

    if (m0 < M) atomicAdd(&out[m0], pair_hsum(acc0));
    if (m1 < M) atomicAdd(&out[m1], pair_hsum(acc1));
}

extern "C" void kernel_launch(void* const* d_in, const int* in_sizes, int n_in,
                              void* d_out, int out_size) {
    const float* points      = (const float*)d_in[0];  // [M,3]
    const float* positions   = (const float*)d_in[1];  // [N,3]
    const float* log_scales  = (const float*)d_in[2];  // [N,3]
    const float* intensities = (const float*)d_in[3];  // [N]
    float* out = (float*)d_out;

    int M = in_sizes[0] / 3;
    int N = in_sizes[3];

    cudaMemsetAsync(out, 0, (size_t)out_size * sizeof(float));

    dim3 grid((M + PTS_PER_BLOCK - 1) / PTS_PER_BLOCK, SEGS);
    size_t smem = (size_t)((N / 2) / SEGS) * 4 * sizeof(float4);
    eval_kernel<<<grid, BLOCK_THREADS, smem>>>(points, positions, log_scales,
                                               intensities, out, M, N);
}